// round 1
// baseline (speedup 1.0000x reference)
#include <cuda_runtime.h>

// ---------------- scratch (device globals: no allocation allowed) ----------
#define MAX_NODES 100000
__device__ __align__(16) float g_sums[(size_t)MAX_NODES * 128];
__device__ float g_counts[MAX_NODES];

typedef unsigned long long ull;

// ---------------- packed f32x2 helpers (sm_100+ PTX) -----------------------
__device__ __forceinline__ ull pack2(float lo, float hi) {
    ull r; asm("mov.b64 %0,{%1,%2};" : "=l"(r) : "f"(lo), "f"(hi)); return r;
}
__device__ __forceinline__ void fma2(ull& d, ull a, ull b) {
    asm("fma.rn.f32x2 %0,%1,%2,%0;" : "+l"(d) : "l"(a), "l"(b));
}
__device__ __forceinline__ float2 unpack2(ull v) {
    float2 f; asm("mov.b64 {%0,%1},%2;" : "=f"(f.x), "=f"(f.y) : "l"(v)); return f;
}

// ---------------- kernel 1: zero the scatter accumulators ------------------
__global__ void zero_kernel(int n_nodes) {
    int i = blockIdx.x * blockDim.x + threadIdx.x;
    int n4 = n_nodes * 32;                       // float4 count for sums
    if (i < n4) ((float4*)g_sums)[i] = make_float4(0.f, 0.f, 0.f, 0.f);
    if (i < n_nodes) g_counts[i] = 0.f;
}

// ---------------- kernel 2: scatter-add edges into nodes -------------------
// One warp per edge; each lane handles a float4 chunk (128 floats / edge).
__global__ void scatter_kernel(const float* __restrict__ edge_attr,
                               const int*   __restrict__ col,
                               int n_edges) {
    int t = blockIdx.x * blockDim.x + threadIdx.x;
    int e = t >> 5;
    int lane = t & 31;
    if (e >= n_edges) return;
    int c = __ldg(col + e);
    float4 v = ((const float4*)edge_attr)[(size_t)e * 32 + lane];
    float* dst = g_sums + (size_t)c * 128 + lane * 4;
    atomicAdd(dst + 0, v.x);
    atomicAdd(dst + 1, v.y);
    atomicAdd(dst + 2, v.z);
    atomicAdd(dst + 3, v.w);
    if (lane == 0) atomicAdd(g_counts + c, 1.0f);
}

// ---------------- kernel 3: fused mean/concat + 3-layer MLP ----------------
// Block = 64 nodes, 256 threads. Activations kept transposed in smem:
//   acts_t[k][node], row stride AST=68 floats (16B-aligned rows).
// Per thread: 8 nodes (ny..ny+7) x (OUT/64) output PAIRS (out = 2*tx + 64*j),
// accumulated as packed f32x2 so the fma pipe runs at 2 MAC/lane/issue.
constexpr int TPB = 256;
constexpr int NPB = 64;
constexpr int AST = 68;   // acts_t row stride in floats
constexpr int SMEM_FLOATS = 256 * AST + 32 * 256;   // acts_t + W chunk
constexpr int SMEM_BYTES  = SMEM_FLOATS * 4;        // 102,400 B

template<int IN, int OUT, bool STORE>
__device__ __forceinline__ void layer(float* acts_t, float* W_s,
                                      const float* __restrict__ W,
                                      const float* __restrict__ b,
                                      float* __restrict__ out_g,
                                      int nbase, int n)
{
    const int tx = threadIdx.x & 31;
    const int ny = (threadIdx.x >> 5) * 8;
    constexpr int J = OUT / 64;                  // output pairs per thread

    ull acc[8][J];
    #pragma unroll
    for (int j = 0; j < J; ++j) {
        float2 bb = __ldg((const float2*)(b + 2 * tx + 64 * j));
        ull bp = pack2(bb.x, bb.y);
        #pragma unroll
        for (int i = 0; i < 8; ++i) acc[i][j] = bp;
    }

    for (int kb = 0; kb < IN / 32; ++kb) {
        // stage 32 rows of W ([32][OUT]) into shared memory (contiguous copy)
        const float4* src = (const float4*)(W + (size_t)kb * 32 * OUT);
        #pragma unroll
        for (int i = threadIdx.x; i < 32 * OUT / 4; i += TPB)
            ((float4*)W_s)[i] = __ldg(src + i);
        __syncthreads();

        #pragma unroll 4
        for (int kk = 0; kk < 32; ++kk) {
            const float* arow = acts_t + (kb * 32 + kk) * AST + ny;
            float4 a0 = *(const float4*)(arow);       // broadcast LDS.128
            float4 a1 = *(const float4*)(arow + 4);
            ull ap[8];
            ap[0] = pack2(a0.x, a0.x); ap[1] = pack2(a0.y, a0.y);
            ap[2] = pack2(a0.z, a0.z); ap[3] = pack2(a0.w, a0.w);
            ap[4] = pack2(a1.x, a1.x); ap[5] = pack2(a1.y, a1.y);
            ap[6] = pack2(a1.z, a1.z); ap[7] = pack2(a1.w, a1.w);
            ull bp[J];
            #pragma unroll
            for (int j = 0; j < J; ++j)
                bp[j] = *(const ull*)(W_s + kk * OUT + 2 * tx + 64 * j);
            #pragma unroll
            for (int i = 0; i < 8; ++i) {
                #pragma unroll
                for (int j = 0; j < J; ++j) fma2(acc[i][j], ap[i], bp[j]);
            }
        }
        __syncthreads();
    }

    if constexpr (STORE) {
        #pragma unroll
        for (int i = 0; i < 8; ++i) {
            int node = nbase + ny + i;
            if (node < n) {
                #pragma unroll
                for (int j = 0; j < J; ++j) {
                    float2 v = unpack2(acc[i][j]);
                    *(float2*)(out_g + (size_t)node * OUT + 2 * tx + 64 * j) = v;
                }
            }
        }
    } else {
        // ReLU + write back transposed for next layer
        #pragma unroll
        for (int i = 0; i < 8; ++i) {
            #pragma unroll
            for (int j = 0; j < J; ++j) {
                float2 v = unpack2(acc[i][j]);
                int o = 2 * tx + 64 * j;
                acts_t[(o + 0) * AST + ny + i] = fmaxf(v.x, 0.f);
                acts_t[(o + 1) * AST + ny + i] = fmaxf(v.y, 0.f);
            }
        }
        __syncthreads();
    }
}

__global__ void __launch_bounds__(TPB, 1)
mlp_kernel(const float* __restrict__ x,
           const float* __restrict__ W1, const float* __restrict__ b1,
           const float* __restrict__ W2, const float* __restrict__ b2,
           const float* __restrict__ W3, const float* __restrict__ b3,
           float* __restrict__ out, int n)
{
    extern __shared__ float smem[];
    float* acts_t = smem;                 // [256][AST]
    float* W_s    = smem + 256 * AST;     // [32][256]

    int nbase = blockIdx.x * NPB;

    // Load concat(x, scatter-mean) transposed into acts_t.
    int f4 = threadIdx.x & 63;            // float4 index within 256-feat row
    for (int nl = threadIdx.x >> 6; nl < NPB; nl += TPB / 64) {
        int node = nbase + nl;
        float4 v = make_float4(0.f, 0.f, 0.f, 0.f);
        if (node < n) {
            if (f4 < 32) {
                v = __ldg((const float4*)x + (size_t)node * 32 + f4);
            } else {
                v = *(((const float4*)g_sums) + (size_t)node * 32 + (f4 - 32));
                float inv = 1.0f / fmaxf(g_counts[node], 1.0f);
                v.x *= inv; v.y *= inv; v.z *= inv; v.w *= inv;
            }
        }
        int f = f4 * 4;
        acts_t[(f + 0) * AST + nl] = v.x;
        acts_t[(f + 1) * AST + nl] = v.y;
        acts_t[(f + 2) * AST + nl] = v.z;
        acts_t[(f + 3) * AST + nl] = v.w;
    }
    __syncthreads();

    layer<256, 256, false>(acts_t, W_s, W1, b1, nullptr, nbase, n);
    layer<256, 256, false>(acts_t, W_s, W2, b2, nullptr, nbase, n);
    layer<256, 128, true >(acts_t, W_s, W3, b3, out,     nbase, n);
}

// ---------------- launcher --------------------------------------------------
extern "C" void kernel_launch(void* const* d_in, const int* in_sizes, int n_in,
                              void* d_out, int out_size)
{
    const float* x          = (const float*)d_in[0];
    const int*   edge_index = (const int*)  d_in[1];
    const float* edge_attr  = (const float*)d_in[2];
    const float* W1 = (const float*)d_in[3];
    const float* b1 = (const float*)d_in[4];
    const float* W2 = (const float*)d_in[5];
    const float* b2 = (const float*)d_in[6];
    const float* W3 = (const float*)d_in[7];
    const float* b3 = (const float*)d_in[8];
    float* out = (float*)d_out;

    int n_nodes = in_sizes[0] / 128;
    int n_edges = in_sizes[1] / 2;
    const int* col = edge_index + n_edges;   // edge_index[1] (destinations)

    cudaFuncSetAttribute(mlp_kernel,
                         cudaFuncAttributeMaxDynamicSharedMemorySize,
                         SMEM_BYTES);

    // 1) zero accumulators
    {
        int n4 = n_nodes * 32;
        int blocks = (n4 + 255) / 256;
        zero_kernel<<<blocks, 256>>>(n_nodes);
    }
    // 2) scatter-add (one warp per edge)
    {
        long long total = (long long)n_edges * 32;
        int blocks = (int)((total + 255) / 256);
        scatter_kernel<<<blocks, 256>>>(edge_attr, col, n_edges);
    }
    // 3) fused mean/concat + MLP
    {
        int blocks = (n_nodes + NPB - 1) / NPB;
        mlp_kernel<<<blocks, TPB, SMEM_BYTES>>>(x, W1, b1, W2, b2, W3, b3,
                                                out, n_nodes);
    }
}

// round 2
// speedup vs baseline: 1.2446x; 1.2446x over previous
#include <cuda_runtime.h>

// ---------------- scratch (device globals: no allocation allowed) ----------
#define MAX_NODES 100000
__device__ __align__(16) float g_sums[(size_t)MAX_NODES * 128];
__device__ float g_counts[MAX_NODES];

typedef unsigned long long ull;

// ---------------- packed f32x2 helpers (sm_100+ PTX) -----------------------
__device__ __forceinline__ ull pack2(float lo, float hi) {
    ull r; asm("mov.b64 %0,{%1,%2};" : "=l"(r) : "f"(lo), "f"(hi)); return r;
}
__device__ __forceinline__ void fma2(ull& d, ull a, ull b) {
    asm("fma.rn.f32x2 %0,%1,%2,%0;" : "+l"(d) : "l"(a), "l"(b));
}
__device__ __forceinline__ float2 unpack2(ull v) {
    float2 f; asm("mov.b64 {%0,%1},%2;" : "=f"(f.x), "=f"(f.y) : "l"(v)); return f;
}

// ---------------- kernel 1: zero the scatter accumulators ------------------
__global__ void zero_kernel(int n_nodes) {
    int i = blockIdx.x * blockDim.x + threadIdx.x;
    int n4 = n_nodes * 32;                       // float4 count for sums
    if (i < n4) ((float4*)g_sums)[i] = make_float4(0.f, 0.f, 0.f, 0.f);
    if (i < n_nodes) g_counts[i] = 0.f;
}

// ---------------- kernel 2: scatter-add edges into nodes -------------------
// One warp per edge; each lane handles one float4 chunk via a single
// packed-vector reduction (red.global.add.v4.f32, sm_90+), 4x fewer
// L2 atomic ops than scalar RED.
__global__ void scatter_kernel(const float* __restrict__ edge_attr,
                               const int*   __restrict__ col,
                               int n_edges) {
    int t = blockIdx.x * blockDim.x + threadIdx.x;
    int e = t >> 5;
    int lane = t & 31;
    if (e >= n_edges) return;
    int c = __ldg(col + e);
    float4 v = ((const float4*)edge_attr)[(size_t)e * 32 + lane];
    float* dst = g_sums + (size_t)c * 128 + lane * 4;
    asm volatile("red.global.add.v4.f32 [%0], {%1,%2,%3,%4};"
                 :: "l"(dst), "f"(v.x), "f"(v.y), "f"(v.z), "f"(v.w)
                 : "memory");
    if (lane == 0) atomicAdd(g_counts + c, 1.0f);
}

// ---------------- kernel 3: fused mean/concat + 3-layer MLP ----------------
// Block = 64 nodes, 256 threads (8 warps), 2 blocks/SM.
// Activations transposed in smem: acts_t[k][node], row stride AST=68 floats.
// Accumulators are packed over NODE pairs: acc[p][j] = (node ny+2p, ny+2p+1)
// for output o = tx + 32*j. A operand loads already-packed via broadcast
// LDS.128; only the B scalar needs the mov.b64 duplication (8 per 32 fma2).
constexpr int TPB = 256;
constexpr int NPB = 64;
constexpr int AST = 68;   // acts_t row stride in floats (16B-aligned rows)
constexpr int SMEM_FLOATS = 256 * AST + 32 * 256;   // acts_t + W chunk
constexpr int SMEM_BYTES  = SMEM_FLOATS * 4;        // 102,400 B

template<int IN, int OUT, bool STORE>
__device__ __forceinline__ void layer(float* acts_t, float* W_s,
                                      const float* __restrict__ W,
                                      const float* __restrict__ b,
                                      float* __restrict__ out_g,
                                      int nbase, int n)
{
    const int tx = threadIdx.x & 31;
    const int ny = (threadIdx.x >> 5) * 8;       // 8 nodes per warp-thread
    constexpr int J = OUT / 32;                  // outputs per thread

    ull acc[4][J];                               // [node-pair][output]
    #pragma unroll
    for (int j = 0; j < J; ++j) {
        float bb = __ldg(b + tx + 32 * j);
        ull bp = pack2(bb, bb);
        #pragma unroll
        for (int p = 0; p < 4; ++p) acc[p][j] = bp;
    }

    for (int kb = 0; kb < IN / 32; ++kb) {
        // stage 32 rows of W ([32][OUT]) into shared memory
        const float4* src = (const float4*)(W + (size_t)kb * 32 * OUT);
        #pragma unroll
        for (int i = threadIdx.x; i < 32 * OUT / 4; i += TPB)
            ((float4*)W_s)[i] = __ldg(src + i);
        __syncthreads();

        #pragma unroll 4
        for (int kk = 0; kk < 32; ++kk) {
            const float* arow = acts_t + (kb * 32 + kk) * AST + ny;
            // nodes ny..ny+7, already adjacent pairs: 2 broadcast LDS.128
            ull ap[4];
            {
                float4 a0 = *(const float4*)(arow);
                float4 a1 = *(const float4*)(arow + 4);
                ap[0] = pack2(a0.x, a0.y); ap[1] = pack2(a0.z, a0.w);
                ap[2] = pack2(a1.x, a1.y); ap[3] = pack2(a1.z, a1.w);
            }
            const float* wrow = W_s + kk * OUT + tx;
            #pragma unroll
            for (int j = 0; j < J; ++j) {
                float wv = wrow[32 * j];          // conflict-free LDS.32
                ull bp = pack2(wv, wv);
                #pragma unroll
                for (int p = 0; p < 4; ++p) fma2(acc[p][j], ap[p], bp);
            }
        }
        __syncthreads();
    }

    if constexpr (STORE) {
        #pragma unroll
        for (int p = 0; p < 4; ++p) {
            int n0 = nbase + ny + 2 * p;
            #pragma unroll
            for (int j = 0; j < J; ++j) {
                float2 v = unpack2(acc[p][j]);
                int o = tx + 32 * j;
                if (n0 < n)     out_g[(size_t)n0 * OUT + o]         = v.x;
                if (n0 + 1 < n) out_g[(size_t)(n0 + 1) * OUT + o]   = v.y;
            }
        }
    } else {
        // ReLU + write back transposed for next layer (float2 per node pair)
        #pragma unroll
        for (int j = 0; j < J; ++j) {
            int o = tx + 32 * j;
            #pragma unroll
            for (int p = 0; p < 4; ++p) {
                float2 v = unpack2(acc[p][j]);
                v.x = fmaxf(v.x, 0.f);
                v.y = fmaxf(v.y, 0.f);
                *(float2*)(acts_t + o * AST + ny + 2 * p) = v;
            }
        }
        __syncthreads();
    }
}

__global__ void __launch_bounds__(TPB, 2)
mlp_kernel(const float* __restrict__ x,
           const float* __restrict__ W1, const float* __restrict__ b1,
           const float* __restrict__ W2, const float* __restrict__ b2,
           const float* __restrict__ W3, const float* __restrict__ b3,
           float* __restrict__ out, int n)
{
    extern __shared__ float smem[];
    float* acts_t = smem;                 // [256][AST]
    float* W_s    = smem + 256 * AST;     // [32][256]

    int nbase = blockIdx.x * NPB;

    // Load concat(x, scatter-mean) transposed into acts_t.
    int f4 = threadIdx.x & 63;            // float4 index within 256-feat row
    for (int nl = threadIdx.x >> 6; nl < NPB; nl += TPB / 64) {
        int node = nbase + nl;
        float4 v = make_float4(0.f, 0.f, 0.f, 0.f);
        if (node < n) {
            if (f4 < 32) {
                v = __ldg((const float4*)x + (size_t)node * 32 + f4);
            } else {
                v = *(((const float4*)g_sums) + (size_t)node * 32 + (f4 - 32));
                float inv = 1.0f / fmaxf(g_counts[node], 1.0f);
                v.x *= inv; v.y *= inv; v.z *= inv; v.w *= inv;
            }
        }
        int f = f4 * 4;
        acts_t[(f + 0) * AST + nl] = v.x;
        acts_t[(f + 1) * AST + nl] = v.y;
        acts_t[(f + 2) * AST + nl] = v.z;
        acts_t[(f + 3) * AST + nl] = v.w;
    }
    __syncthreads();

    layer<256, 256, false>(acts_t, W_s, W1, b1, nullptr, nbase, n);
    layer<256, 256, false>(acts_t, W_s, W2, b2, nullptr, nbase, n);
    layer<256, 128, true >(acts_t, W_s, W3, b3, out,     nbase, n);
}

// ---------------- launcher --------------------------------------------------
extern "C" void kernel_launch(void* const* d_in, const int* in_sizes, int n_in,
                              void* d_out, int out_size)
{
    const float* x          = (const float*)d_in[0];
    const int*   edge_index = (const int*)  d_in[1];
    const float* edge_attr  = (const float*)d_in[2];
    const float* W1 = (const float*)d_in[3];
    const float* b1 = (const float*)d_in[4];
    const float* W2 = (const float*)d_in[5];
    const float* b2 = (const float*)d_in[6];
    const float* W3 = (const float*)d_in[7];
    const float* b3 = (const float*)d_in[8];
    float* out = (float*)d_out;

    int n_nodes = in_sizes[0] / 128;
    int n_edges = in_sizes[1] / 2;
    const int* col = edge_index + n_edges;   // edge_index[1] (destinations)

    cudaFuncSetAttribute(mlp_kernel,
                         cudaFuncAttributeMaxDynamicSharedMemorySize,
                         SMEM_BYTES);

    // 1) zero accumulators
    {
        int n4 = n_nodes * 32;
        int blocks = (n4 + 255) / 256;
        zero_kernel<<<blocks, 256>>>(n_nodes);
    }
    // 2) scatter-add (one warp per edge, vector atomics)
    {
        long long total = (long long)n_edges * 32;
        int blocks = (int)((total + 255) / 256);
        scatter_kernel<<<blocks, 256>>>(edge_attr, col, n_edges);
    }
    // 3) fused mean/concat + MLP
    {
        int blocks = (n_nodes + NPB - 1) / NPB;
        mlp_kernel<<<blocks, TPB, SMEM_BYTES>>>(x, W1, b1, W2, b2, W3, b3,
                                                out, n_nodes);
    }
}

// round 4
// speedup vs baseline: 1.9006x; 1.5271x over previous
#include <cuda_runtime.h>
#include <cuda_bf16.h>
#include <cstdint>

// ---------------- scratch (device globals: no allocation allowed) ----------
#define MAX_NODES 100000
__device__ __align__(16) float g_sums[(size_t)MAX_NODES * 128];
__device__ float g_counts[MAX_NODES];
// Transposed, k-chunked bf16 hi/lo weights:
// per layer: [kc][split][n][32] ; L1 @0 (131072), L2 @131072, L3 @262144
__device__ __align__(16) __nv_bfloat16 g_Wt[327680];

// ---------------- helpers ---------------------------------------------------
__device__ __forceinline__ uint32_t smem_u32(const void* p) {
    uint32_t a;
    asm("{ .reg .u64 t; cvta.to.shared.u64 t, %1; cvt.u32.u64 %0, t; }"
        : "=r"(a) : "l"(p));
    return a;
}
__device__ __forceinline__ void cp_async16(uint32_t saddr, const void* g) {
    asm volatile("cp.async.cg.shared.global [%0], [%1], 16;" :: "r"(saddr), "l"(g));
}
__device__ __forceinline__ void ldm_x4(uint32_t* r, uint32_t addr) {
    asm volatile("ldmatrix.sync.aligned.m8n8.x4.shared.b16 {%0,%1,%2,%3}, [%4];"
        : "=r"(r[0]), "=r"(r[1]), "=r"(r[2]), "=r"(r[3]) : "r"(addr));
}
__device__ __forceinline__ void mma_bf16(float* c, const uint32_t* a,
                                         uint32_t b0, uint32_t b1) {
    asm volatile("mma.sync.aligned.m16n8k16.row.col.f32.bf16.bf16.f32 "
        "{%0,%1,%2,%3}, {%4,%5,%6,%7}, {%8,%9}, {%0,%1,%2,%3};"
        : "+f"(c[0]), "+f"(c[1]), "+f"(c[2]), "+f"(c[3])
        : "r"(a[0]), "r"(a[1]), "r"(a[2]), "r"(a[3]), "r"(b0), "r"(b1));
}
__device__ __forceinline__ uint32_t pack_bf(__nv_bfloat16 a, __nv_bfloat16 b) {
    return (uint32_t)__bfloat16_as_ushort(a) | ((uint32_t)__bfloat16_as_ushort(b) << 16);
}

// smem layout (bytes)
constexpr int AS       = 264;                 // A row stride (elements)
constexpr int A_HI_OFF = 0;                   // 128*264*2 = 67584
constexpr int A_LO_OFF = 67584;
constexpr int B_OFF    = 135168;
constexpr int BUFSZ    = 40960;               // one B buffer (OUT=256 worst case)
constexpr int SMEM_TOTAL = B_OFF + 2 * BUFSZ; // 217088

__device__ __forceinline__ void store_split(char* smem, int row, int col,
                                            float v0, float v1) {
    __nv_bfloat16 h0 = __float2bfloat16(v0), h1 = __float2bfloat16(v1);
    __nv_bfloat16 l0 = __float2bfloat16(v0 - __bfloat162float(h0));
    __nv_bfloat16 l1 = __float2bfloat16(v1 - __bfloat162float(h1));
    uint32_t off = (uint32_t)(row * AS + col) * 2;
    *(uint32_t*)(smem + A_HI_OFF + off) = pack_bf(h0, h1);
    *(uint32_t*)(smem + A_LO_OFF + off) = pack_bf(l0, l1);
}

// ---------------- kernel 1: zero the scatter accumulators ------------------
__global__ void zero_kernel(int n_nodes) {
    int i = blockIdx.x * blockDim.x + threadIdx.x;
    int n4 = n_nodes * 32;
    if (i < n4) ((float4*)g_sums)[i] = make_float4(0.f, 0.f, 0.f, 0.f);
    if (i < n_nodes) g_counts[i] = 0.f;
}

// ---------------- kernel 2: scatter-add (vector atomics) -------------------
__global__ void scatter_kernel(const float* __restrict__ edge_attr,
                               const int*   __restrict__ col,
                               int n_edges) {
    int t = blockIdx.x * blockDim.x + threadIdx.x;
    int e = t >> 5;
    int lane = t & 31;
    if (e >= n_edges) return;
    int c = __ldg(col + e);
    float4 v = ((const float4*)edge_attr)[(size_t)e * 32 + lane];
    float* dst = g_sums + (size_t)c * 128 + lane * 4;
    asm volatile("red.global.add.v4.f32 [%0], {%1,%2,%3,%4};"
                 :: "l"(dst), "f"(v.x), "f"(v.y), "f"(v.z), "f"(v.w) : "memory");
    if (lane == 0) atomicAdd(g_counts + c, 1.0f);
}

// ---------------- kernel: prep weights -> g_Wt ------------------------------
// Layout per layer: [kc][split(hi=0,lo=1)][n][32 k] , n-major rows (W^T).
__global__ void prep_kernel(const float* __restrict__ W1,
                            const float* __restrict__ W2,
                            const float* __restrict__ W3) {
    int i = blockIdx.x * blockDim.x + threadIdx.x;
    if (i >= 327680) return;
    const float* W; int base, OUT, e = i;
    if (i < 131072)      { W = W1; base = 0;      OUT = 256; }
    else if (i < 262144) { W = W2; base = 131072; OUT = 256; e -= 131072; }
    else                 { W = W3; base = 262144; OUT = 128; e -= 262144; }
    int per_kc = 2 * OUT * 32;
    int kc  = e / per_kc;
    int rem = e % per_kc;
    int s   = rem / (OUT * 32);
    int r   = rem % (OUT * 32);
    int nn  = r >> 5, kk = r & 31;
    int k   = kc * 32 + kk;
    float w = __ldg(W + (size_t)k * OUT + nn);
    __nv_bfloat16 hi = __float2bfloat16(w);
    __nv_bfloat16 val = s ? __float2bfloat16(w - __bfloat162float(hi)) : hi;
    g_Wt[base + e] = val;
}

// ---------------- B chunk loader (linear cp.async into padded rows) --------
template<int OUT>
__device__ __forceinline__ void load_chunk(uint32_t bdst, const __nv_bfloat16* gsrc) {
    constexpr int UNITS = OUT * 8;         // 16B units in a chunk (both splits)
    constexpr int SSTR  = OUT * 80;        // bytes per split in smem
    for (int u = threadIdx.x; u < UNITS; u += 512) {
        int s = u / (UNITS / 2);
        int v = u % (UNITS / 2);
        int nn = v >> 2, part = v & 3;
        uint32_t dst = bdst + s * SSTR + nn * 80 + part * 16;
        cp_async16(dst, (const char*)gsrc + (size_t)u * 16);
    }
    asm volatile("cp.async.commit_group;");
}

// ---------------- one MLP layer on HMMA -------------------------------------
template<int OUT, bool LAST>
__device__ __forceinline__ void run_layer(char* smem, uint32_t sm_base,
                                          const __nv_bfloat16* gW,
                                          const float* __restrict__ bias,
                                          float* __restrict__ out_g,
                                          int nbase, int n)
{
    const int lane = threadIdx.x & 31, wid = threadIdx.x >> 5;
    const int wm = wid >> 2, wn = wid & 3;
    constexpr int NT   = OUT / 32;          // n8-tiles per warp
    constexpr int SSTR = OUT * 80;          // bytes per split in a B buffer

    const int arow = wm * 32 + (lane & 15);
    const int acol = (lane >> 4) * 8;

    float acc[2][NT][4];
    #pragma unroll
    for (int mt = 0; mt < 2; ++mt)
        #pragma unroll
        for (int nt = 0; nt < NT; ++nt)
            #pragma unroll
            for (int c = 0; c < 4; ++c) acc[mt][nt][c] = 0.f;

    load_chunk<OUT>(sm_base + B_OFF, gW);   // chunk 0 -> buffer 0

    for (int kc = 0; kc < 8; ++kc) {
        int buf = kc & 1;
        if (kc < 7) {
            load_chunk<OUT>(sm_base + B_OFF + (1 - buf) * BUFSZ,
                            gW + (size_t)(kc + 1) * 2 * OUT * 32);
            asm volatile("cp.async.wait_group 1;");
        } else {
            asm volatile("cp.async.wait_group 0;");
        }
        __syncthreads();                     // chunk kc visible to all

        const char* bb = smem + B_OFF + buf * BUFSZ;
        #pragma unroll
        for (int ks = 0; ks < 2; ++ks) {
            const int k0 = kc * 32 + ks * 16;
            uint32_t ahi[2][4], alo[2][4];
            #pragma unroll
            for (int mt = 0; mt < 2; ++mt) {
                uint32_t aaddr = sm_base +
                    (uint32_t)(((arow + mt * 16) * AS + k0 + acol) * 2);
                ldm_x4(ahi[mt], aaddr + A_HI_OFF);
                ldm_x4(alo[mt], aaddr + A_LO_OFF);
            }
            #pragma unroll
            for (int nt = 0; nt < NT; ++nt) {
                int ncol = wn * (NT * 8) + nt * 8 + (lane >> 2);
                int koff = (ks * 16 + (lane & 3) * 2) * 2;
                const char* bp = bb + ncol * 80 + koff;
                uint32_t bh0 = *(const uint32_t*)(bp);
                uint32_t bh1 = *(const uint32_t*)(bp + 16);
                uint32_t bl0 = *(const uint32_t*)(bp + SSTR);
                uint32_t bl1 = *(const uint32_t*)(bp + SSTR + 16);
                #pragma unroll
                for (int mt = 0; mt < 2; ++mt) {
                    mma_bf16(acc[mt][nt], ahi[mt], bh0, bh1);
                    mma_bf16(acc[mt][nt], alo[mt], bh0, bh1);
                    mma_bf16(acc[mt][nt], ahi[mt], bl0, bl1);
                }
            }
        }
        __syncthreads();                     // all reads of buf done before reuse
    }

    // epilogue (k-loop final __syncthreads already done)
    #pragma unroll
    for (int mt = 0; mt < 2; ++mt) {
        int row0 = wm * 32 + mt * 16 + (lane >> 2);
        #pragma unroll
        for (int nt = 0; nt < NT; ++nt) {
            int col = wn * (NT * 8) + nt * 8 + (lane & 3) * 2;
            float bv0 = __ldg(bias + col), bv1 = __ldg(bias + col + 1);
            float v0 = acc[mt][nt][0] + bv0, v1 = acc[mt][nt][1] + bv1;
            float v2 = acc[mt][nt][2] + bv0, v3 = acc[mt][nt][3] + bv1;
            if (LAST) {
                int n0 = nbase + row0, n1 = n0 + 8;
                if (n0 < n) {
                    float2 t = {v0, v1};
                    *(float2*)(out_g + (size_t)n0 * OUT + col) = t;
                }
                if (n1 < n) {
                    float2 t = {v2, v3};
                    *(float2*)(out_g + (size_t)n1 * OUT + col) = t;
                }
            } else {
                store_split(smem, row0,     col, fmaxf(v0, 0.f), fmaxf(v1, 0.f));
                store_split(smem, row0 + 8, col, fmaxf(v2, 0.f), fmaxf(v3, 0.f));
            }
        }
    }
    if (!LAST) __syncthreads();
}

// ---------------- kernel 3: HMMA MLP ----------------------------------------
__global__ void __launch_bounds__(512, 1)
mlp_mma_kernel(const float* __restrict__ x,
               const float* __restrict__ b1, const float* __restrict__ b2,
               const float* __restrict__ b3,
               float* __restrict__ out, int n)
{
    extern __shared__ char smem[];
    const uint32_t sm_base = smem_u32(smem);
    const int tid = threadIdx.x;
    const int nbase = blockIdx.x * 128;

    // Build A = concat(x, scatter-mean) as bf16 hi/lo, padded rows.
    {
        int m = tid >> 2, q = tid & 3;
        int node = nbase + m;
        bool valid = node < n;
        const float4* src = (q < 2)
            ? (const float4*)x      + (size_t)node * 32 + q * 16
            : (const float4*)g_sums + (size_t)node * 32 + (q - 2) * 16;
        float inv = 1.f;
        if (valid && q >= 2) inv = 1.f / fmaxf(g_counts[node], 1.f);
        #pragma unroll 4
        for (int f = 0; f < 16; ++f) {
            float4 v = make_float4(0.f, 0.f, 0.f, 0.f);
            if (valid) {
                v = __ldg(src + f);
                if (q >= 2) { v.x *= inv; v.y *= inv; v.z *= inv; v.w *= inv; }
            }
            int col = q * 64 + f * 4;
            store_split(smem, m, col,     v.x, v.y);
            store_split(smem, m, col + 2, v.z, v.w);
        }
    }
    __syncthreads();

    run_layer<256, false>(smem, sm_base, g_Wt,          b1, nullptr, nbase, n);
    run_layer<256, false>(smem, sm_base, g_Wt + 131072, b2, nullptr, nbase, n);
    run_layer<128, true >(smem, sm_base, g_Wt + 262144, b3, out,     nbase, n);
}

// ---------------- launcher --------------------------------------------------
extern "C" void kernel_launch(void* const* d_in, const int* in_sizes, int n_in,
                              void* d_out, int out_size)
{
    const float* x          = (const float*)d_in[0];
    const int*   edge_index = (const int*)  d_in[1];
    const float* edge_attr  = (const float*)d_in[2];
    const float* W1 = (const float*)d_in[3];
    const float* b1 = (const float*)d_in[4];
    const float* W2 = (const float*)d_in[5];
    const float* b2 = (const float*)d_in[6];
    const float* W3 = (const float*)d_in[7];
    const float* b3 = (const float*)d_in[8];
    float* out = (float*)d_out;

    int n_nodes = in_sizes[0] / 128;
    int n_edges = in_sizes[1] / 2;
    const int* col = edge_index + n_edges;

    cudaFuncSetAttribute(mlp_mma_kernel,
                         cudaFuncAttributeMaxDynamicSharedMemorySize, SMEM_TOTAL);

    // 1) zero accumulators
    {
        int n4 = n_nodes * 32;
        zero_kernel<<<(n4 + 255) / 256, 256>>>(n_nodes);
    }
    // 2) prep weights (bf16 hi/lo, transposed + k-chunked)
    prep_kernel<<<1280, 256>>>(W1, W2, W3);
    // 3) scatter-add
    {
        long long total = (long long)n_edges * 32;
        scatter_kernel<<<(int)((total + 255) / 256), 256>>>(edge_attr, col, n_edges);
    }
    // 4) HMMA MLP
    {
        int blocks = (n_nodes + 127) / 128;
        mlp_mma_kernel<<<blocks, 512, SMEM_TOTAL>>>(x, b1, b2, b3, out, n_nodes);
    }
}